// round 2
// baseline (speedup 1.0000x reference)
#include <cuda_runtime.h>
#include <math.h>

// Problem constants
#define N_   32
#define C_   256
#define HW_  4096
#define G_   4
#define D_   64
#define MTOT 131072.0f      // G-group column count: N*H*W
#define EPSW 1e-5f          // CE eps
#define LNEPS 1e-5f

// ---------------- device scratch (no allocations allowed) ----------------
__device__ float d_sum  [N_*C_];
__device__ float d_sumsq[N_*C_];
__device__ float d_gram [G_*D_*D_];
__device__ float d_a    [N_*C_];   // (1-w)*y/scale
__device__ float d_mu   [C_];      // per-channel mean over m
__device__ float d_wP   [G_*D_*D_];
__device__ float d_w;

// ---------------- K0: zero the gram accumulators (per launch!) -----------
__global__ void k_zero() {
    int i = blockIdx.x * blockDim.x + threadIdx.x;
    if (i < G_*D_*D_) d_gram[i] = 0.0f;
}

// ---------------- K1: per-(n,c) sum / sumsq over HW -----------------------
__global__ void k_rowstats(const float* __restrict__ X) {
    int row = blockIdx.x;                       // 0..8191  (n*C + c)
    const float4* p = reinterpret_cast<const float4*>(X + (size_t)row * HW_);
    int tid = threadIdx.x;
    float s = 0.0f, s2 = 0.0f;
    #pragma unroll
    for (int k = 0; k < 4; ++k) {
        float4 v = p[tid + k * 256];
        s  += v.x + v.y + v.z + v.w;
        s2 += v.x*v.x + v.y*v.y + v.z*v.z + v.w*v.w;
    }
    #pragma unroll
    for (int o = 16; o; o >>= 1) {
        s  += __shfl_xor_sync(0xffffffffu, s,  o);
        s2 += __shfl_xor_sync(0xffffffffu, s2, o);
    }
    __shared__ float ss[8], ss2[8];
    int w = tid >> 5;
    if ((tid & 31) == 0) { ss[w] = s; ss2[w] = s2; }
    __syncthreads();
    if (tid == 0) {
        float a = 0.0f, b = 0.0f;
        #pragma unroll
        for (int i = 0; i < 8; ++i) { a += ss[i]; b += ss2[i]; }
        d_sum[row] = a; d_sumsq[row] = b;
    }
}

// ---------------- K2: xvar -> MLP -> y -> a ; channel means; w ------------
__global__ void k_stats(const float* __restrict__ fc1, const float* __restrict__ lng,
                        const float* __restrict__ lnb, const float* __restrict__ fc2,
                        const float* __restrict__ xw) {
    __shared__ float xv[N_*C_];     // 32 KB
    __shared__ float h [N_*D_];     // 8 KB
    __shared__ float red[256];
    __shared__ float s_scale;
    int tid = threadIdx.x;

    float acc = 0.0f;
    for (int i = tid; i < N_*C_; i += 256) {
        float s = d_sum[i], s2 = d_sumsq[i];
        float v = (s2 - s * s * (1.0f / HW_)) * (1.0f / (HW_ - 1));  // unbiased var
        xv[i] = v;
        acc += v;
    }
    red[tid] = acc;
    __syncthreads();
    for (int off = 128; off; off >>= 1) {
        if (tid < off) red[tid] += red[tid + off];
        __syncthreads();
    }
    if (tid == 0) s_scale = sqrtf(red[0] * (1.0f / (N_*C_)));

    // channel means over m  (mean over n of per-(n,c) means)
    {
        float m = 0.0f;
        for (int n = 0; n < N_; ++n) m += d_sum[n * C_ + tid];
        d_mu[tid] = m * (1.0f / MTOT);
    }
    __syncthreads();

    // h = xvar @ fc1^T : [32, 64]
    for (int t = 0; t < 8; ++t) {
        int idx = tid + t * 256;          // 0..2047
        int n = idx >> 6, j = idx & 63;
        const float* w = fc1 + j * C_;
        const float* x = xv  + n * C_;
        float a = 0.0f;
        for (int c = 0; c < C_; ++c) a += x[c] * w[c];
        h[idx] = a;
    }
    __syncthreads();

    // LayerNorm (biased var) + affine + relu, per row n
    if (tid < N_) {
        float m = 0.0f, m2 = 0.0f;
        for (int j = 0; j < D_; ++j) { float v = h[tid*D_ + j]; m += v; m2 += v*v; }
        m  *= (1.0f / D_);
        m2  = m2 * (1.0f / D_) - m * m;
        float inv = rsqrtf(m2 + LNEPS);
        for (int j = 0; j < D_; ++j) {
            float v = (h[tid*D_ + j] - m) * inv * lng[j] + lnb[j];
            h[tid*D_ + j] = v > 0.0f ? v : 0.0f;
        }
    }
    __syncthreads();

    float w_ = 1.0f / (1.0f + expf(-xw[0]));
    if (tid == 0) d_w = w_;
    float coef = (1.0f - w_) / s_scale;
    for (int i = tid; i < N_*C_; i += 256) {
        int n = i >> 8, c = i & 255;
        const float* ww = fc2 + c * D_;
        const float* hh = h   + n * D_;
        float a = 0.0f;
        for (int j = 0; j < D_; ++j) a += hh[j] * ww[j];
        float y = 1.0f / (1.0f + expf(-a));
        d_a[i] = coef * y;
    }
}

// ---------------- K3: per-group Gram = sum_m x x^T (uncentered) -----------
// grid (chunk=4, n=32, g=4), 256 threads; chunk = 1024 positions = 16 tiles of 64
__global__ void __launch_bounds__(256) k_gram(const float* __restrict__ X) {
    int chunk = blockIdx.x, n = blockIdx.y, g = blockIdx.z;
    __shared__ float xs[D_ * 65];              // channel-major, pad 65 -> conflict-free
    int tid = threadIdx.x;
    int tx = tid & 15, ty = tid >> 4;
    int d0 = ty * 4, e0 = tx * 4;
    float acc[4][4] = {};
    const float* base = X + ((size_t)n * C_ + (size_t)g * D_) * HW_ + chunk * 1024;

    for (int t = 0; t < 16; ++t) {
        const float* src = base + t * 64;
        #pragma unroll
        for (int k = 0; k < 16; ++k) {
            int idx = tid + k * 256;
            int c = idx >> 6, s = idx & 63;
            xs[c * 65 + s] = src[(size_t)c * HW_ + s];
        }
        __syncthreads();
        #pragma unroll 4
        for (int s = 0; s < 64; ++s) {
            float a0 = xs[(d0+0)*65 + s], a1 = xs[(d0+1)*65 + s];
            float a2 = xs[(d0+2)*65 + s], a3 = xs[(d0+3)*65 + s];
            float b0 = xs[(e0+0)*65 + s], b1 = xs[(e0+1)*65 + s];
            float b2 = xs[(e0+2)*65 + s], b3 = xs[(e0+3)*65 + s];
            acc[0][0] += a0*b0; acc[0][1] += a0*b1; acc[0][2] += a0*b2; acc[0][3] += a0*b3;
            acc[1][0] += a1*b0; acc[1][1] += a1*b1; acc[1][2] += a1*b2; acc[1][3] += a1*b3;
            acc[2][0] += a2*b0; acc[2][1] += a2*b1; acc[2][2] += a2*b2; acc[2][3] += a2*b3;
            acc[3][0] += a3*b0; acc[3][1] += a3*b1; acc[3][2] += a3*b2; acc[3][3] += a3*b3;
        }
        __syncthreads();
    }
    float* gp = d_gram + g * D_ * D_;
    #pragma unroll
    for (int i = 0; i < 4; ++i)
        #pragma unroll
        for (int j = 0; j < 4; ++j)
            atomicAdd(&gp[(d0+i) * D_ + e0 + j], acc[i][j]);
}

// ---------------- K4: Sigma -> Newton-Schulz -> wP ------------------------
__device__ __forceinline__ void mm64(float* Cm, const float* A, const float* B, int tid) {
    for (int t = 0; t < 16; ++t) {
        int idx = tid + t * 256;
        int d = idx >> 6, e = idx & 63;
        float a = 0.0f;
        #pragma unroll 8
        for (int k = 0; k < 64; ++k) a += A[d*65 + k] * B[k*65 + e];
        Cm[d*65 + e] = a;
    }
}

__global__ void k_newton() {
    extern __shared__ float sm[];
    float* SigN = sm;
    float* P    = sm + 4160;
    float* T1   = sm + 8320;
    float* T2   = sm + 12480;
    __shared__ float s_invtr;
    int g = blockIdx.x, tid = threadIdx.x;
    float w = d_w;

    for (int t = 0; t < 16; ++t) {
        int idx = tid + t * 256;
        int d = idx >> 6, e = idx & 63;
        float mu_d = d_mu[g*64 + d], mu_e = d_mu[g*64 + e];
        float v = EPSW * (d_gram[g*4096 + idx] - MTOT * mu_d * mu_e);
        if (d == e) v += 1.0f / MTOT;
        T1[d*65 + e] = v;
        P [d*65 + e] = (d == e) ? 1.0f : 0.0f;
    }
    __syncthreads();
    if (tid == 0) {
        float tr = 0.0f;
        for (int d = 0; d < 64; ++d) tr += T1[d*65 + d];
        s_invtr = 1.0f / tr;
    }
    __syncthreads();
    float invtr = s_invtr;
    for (int t = 0; t < 16; ++t) {
        int idx = tid + t * 256;
        int d = idx >> 6, e = idx & 63;
        SigN[d*65 + e] = T1[d*65 + e] * invtr;
    }
    __syncthreads();

    for (int it = 0; it < 3; ++it) {
        mm64(T1, P, P, tid);    __syncthreads();   // T1 = P^2
        mm64(T2, T1, P, tid);   __syncthreads();   // T2 = P^3
        mm64(T1, T2, SigN, tid);__syncthreads();   // T1 = P^3 * SigN
        for (int t = 0; t < 16; ++t) {
            int idx = tid + t * 256;
            int d = idx >> 6, e = idx & 63;
            P[d*65 + e] = -0.5f * P[d*65 + e] + 1.5f * T1[d*65 + e];
        }
        __syncthreads();
    }
    for (int t = 0; t < 16; ++t) {
        int idx = tid + t * 256;
        int d = idx >> 6, e = idx & 63;
        d_wP[g*4096 + idx] = w * P[d*65 + e];
    }
}

// ---------------- K5: out = (wP[g] + diag(a[n])) @ x ----------------------
// grid (chunk=8, n=32, g=4), 256 threads; chunk = 512 positions = 8 tiles of 64
__global__ void __launch_bounds__(256) k_apply(const float* __restrict__ X,
                                               float* __restrict__ out) {
    int chunk = blockIdx.x, n = blockIdx.y, g = blockIdx.z;
    __shared__ float Msm[D_ * 65];
    __shared__ float xs [D_ * 65];
    int tid = threadIdx.x;

    for (int t = 0; t < 16; ++t) {
        int idx = tid + t * 256;
        int d = idx >> 6, e = idx & 63;
        float v = d_wP[g*4096 + idx];
        if (d == e) v += d_a[n * C_ + g*64 + d];
        Msm[d*65 + e] = v;
    }

    int tx = tid & 15, ty = tid >> 4;
    int d0 = 4 * ty, s0 = 4 * tx;
    const float* base  = X   + ((size_t)n * C_ + (size_t)g * D_) * HW_ + chunk * 512;
    float*       obase = out + ((size_t)n * C_ + (size_t)g * D_) * HW_ + chunk * 512;

    for (int t = 0; t < 8; ++t) {
        const float* src = base + t * 64;
        __syncthreads();                    // Msm ready / xs free
        #pragma unroll
        for (int k = 0; k < 16; ++k) {
            int idx = tid + k * 256;
            int c = idx >> 6, s = idx & 63;
            xs[c*65 + s] = src[(size_t)c * HW_ + s];
        }
        __syncthreads();

        float acc[4][4] = {};
        #pragma unroll 4
        for (int e = 0; e < 64; ++e) {
            float a0 = Msm[(d0+0)*65 + e], a1 = Msm[(d0+1)*65 + e];
            float a2 = Msm[(d0+2)*65 + e], a3 = Msm[(d0+3)*65 + e];
            float b0 = xs[e*65 + s0+0], b1 = xs[e*65 + s0+1];
            float b2 = xs[e*65 + s0+2], b3 = xs[e*65 + s0+3];
            acc[0][0] += a0*b0; acc[0][1] += a0*b1; acc[0][2] += a0*b2; acc[0][3] += a0*b3;
            acc[1][0] += a1*b0; acc[1][1] += a1*b1; acc[1][2] += a1*b2; acc[1][3] += a1*b3;
            acc[2][0] += a2*b0; acc[2][1] += a2*b1; acc[2][2] += a2*b2; acc[2][3] += a2*b3;
            acc[3][0] += a3*b0; acc[3][1] += a3*b1; acc[3][2] += a3*b2; acc[3][3] += a3*b3;
        }
        float* dst = obase + t * 64;
        #pragma unroll
        for (int i = 0; i < 4; ++i) {
            float4 v = make_float4(acc[i][0], acc[i][1], acc[i][2], acc[i][3]);
            *reinterpret_cast<float4*>(dst + (size_t)(d0+i) * HW_ + s0) = v;
        }
    }
}

// ---------------- launch ---------------------------------------------------
extern "C" void kernel_launch(void* const* d_in, const int* in_sizes, int n_in,
                              void* d_out, int out_size) {
    const float* X    = (const float*)d_in[0];
    const float* fc1  = (const float*)d_in[1];
    const float* lng  = (const float*)d_in[2];
    const float* lnb  = (const float*)d_in[3];
    const float* fc2  = (const float*)d_in[4];
    const float* xw   = (const float*)d_in[5];
    float* out = (float*)d_out;

    static bool attr_set = false;
    if (!attr_set) {
        cudaFuncSetAttribute(k_newton, cudaFuncAttributeMaxDynamicSharedMemorySize, 67584);
        attr_set = true;
    }

    k_zero<<<64, 256>>>();
    k_rowstats<<<N_*C_, 256>>>(X);
    k_gram<<<dim3(4, 32, 4), 256>>>(X);
    k_stats<<<1, 256>>>(fc1, lng, lnb, fc2, xw);
    k_newton<<<G_, 256, 66560>>>();
    k_apply<<<dim3(8, 32, 4), 256>>>(X, out);
}

// round 3
// speedup vs baseline: 2.9675x; 2.9675x over previous
#include <cuda_runtime.h>
#include <math.h>

#define N_   32
#define C_   256
#define HW_  4096
#define G_   4
#define D_   64
#define MTOT 131072.0f
#define EPSW 1e-5f
#define LNEPS 1e-5f

typedef unsigned long long ull;

__device__ __forceinline__ void fma2(ull& d, ull a, ull b) {
    asm("fma.rn.f32x2 %0, %1, %2, %0;" : "+l"(d) : "l"(a), "l"(b));
}
__device__ __forceinline__ void add2(ull& d, ull a) {
    asm("add.rn.f32x2 %0, %0, %1;" : "+l"(d) : "l"(a));
}
__device__ __forceinline__ float2 u2f(ull v) {
    float2 r;
    asm("mov.b64 {%0,%1}, %2;" : "=f"(r.x), "=f"(r.y) : "l"(v));
    return r;
}

// ---------------- device scratch ----------------
__device__ float d_sum  [N_*C_];
__device__ float d_sumsq[N_*C_];
__device__ float d_gram [G_*D_*D_];
__device__ float d_xv   [N_*C_];
__device__ float d_a    [N_*C_];
__device__ float d_mu   [C_];
__device__ float d_wP   [G_*D_*D_];
__device__ float d_w;
__device__ float d_coef;

// ---------------- K0: zero accumulators (every launch) ----------------
__global__ void k_zero() {
    int i = blockIdx.x * blockDim.x + threadIdx.x;
    if (i < N_*C_) { d_sum[i] = 0.0f; d_sumsq[i] = 0.0f; }
    if (i < G_*D_*D_) d_gram[i] = 0.0f;
}

// ---------------- K1: gram + fused row stats ----------------
// grid (chunk=4, n=32, g=4), 256 threads. chunk = 1024 positions = 16 tiles of 64.
// xs: channel-major [64][66] (pad 66: even for float2 alignment, conflict-free
// with lane-stride-1 tile mapping d=ty+16i / e=tx+16j).
__global__ void __launch_bounds__(256) k_gram(const float* __restrict__ X) {
    int chunk = blockIdx.x, n = blockIdx.y, g = blockIdx.z;
    __shared__ __align__(16) float xs[D_ * 66];
    __shared__ float rs[256], rs2[256];
    int tid = threadIdx.x;
    int tx = tid & 15, ty = tid >> 4;
    int cs = tid & 63, q = tid >> 6;

    ull acc[4][4] = {};
    ull s_acc = 0ull, s2_acc = 0ull;
    const float* base = X + ((size_t)n * C_ + (size_t)g * D_) * HW_ + chunk * 1024;

    for (int t = 0; t < 16; ++t) {
        const float* src = base + t * 64;
        #pragma unroll
        for (int k = 0; k < 16; ++k) {
            int idx = tid + k * 256;
            int c = idx >> 6, s = idx & 63;
            xs[c * 66 + s] = src[(size_t)c * HW_ + s];
        }
        __syncthreads();
        const ull* xa = (const ull*)xs;          // float2 index: c*33 + u
        #pragma unroll 4
        for (int u = 0; u < 32; ++u) {
            ull a0 = xa[(ty     )*33 + u], a1 = xa[(ty + 16)*33 + u];
            ull a2 = xa[(ty + 32)*33 + u], a3 = xa[(ty + 48)*33 + u];
            ull b0 = xa[(tx     )*33 + u], b1 = xa[(tx + 16)*33 + u];
            ull b2 = xa[(tx + 32)*33 + u], b3 = xa[(tx + 48)*33 + u];
            fma2(acc[0][0], a0, b0); fma2(acc[0][1], a0, b1);
            fma2(acc[0][2], a0, b2); fma2(acc[0][3], a0, b3);
            fma2(acc[1][0], a1, b0); fma2(acc[1][1], a1, b1);
            fma2(acc[1][2], a1, b2); fma2(acc[1][3], a1, b3);
            fma2(acc[2][0], a2, b0); fma2(acc[2][1], a2, b1);
            fma2(acc[2][2], a2, b2); fma2(acc[2][3], a2, b3);
            fma2(acc[3][0], a3, b0); fma2(acc[3][1], a3, b1);
            fma2(acc[3][2], a3, b2); fma2(acc[3][3], a3, b3);
        }
        // fused per-channel stats: thread covers channel cs, s-quarter q
        #pragma unroll
        for (int u = 8 * q; u < 8 * q + 8; ++u) {
            ull v = xa[cs * 33 + u];
            add2(s_acc, v);
            fma2(s2_acc, v, v);
        }
        __syncthreads();
    }

    float2 sv = u2f(s_acc), s2v = u2f(s2_acc);
    rs[tid] = sv.x + sv.y; rs2[tid] = s2v.x + s2v.y;
    __syncthreads();
    if (tid < 64) {
        float a = rs[tid] + rs[tid+64] + rs[tid+128] + rs[tid+192];
        float b = rs2[tid] + rs2[tid+64] + rs2[tid+128] + rs2[tid+192];
        atomicAdd(&d_sum  [n * C_ + g * 64 + tid], a);
        atomicAdd(&d_sumsq[n * C_ + g * 64 + tid], b);
    }
    float* gp = d_gram + g * D_ * D_;
    #pragma unroll
    for (int i = 0; i < 4; ++i)
        #pragma unroll
        for (int j = 0; j < 4; ++j) {
            float2 f = u2f(acc[i][j]);
            atomicAdd(&gp[(ty + 16*i) * D_ + tx + 16*j], f.x + f.y);
        }
}

// ---------------- K2: xvar, scale, mu, w (tiny, 1 block) ----------------
__global__ void k_prep(const float* __restrict__ xw) {
    __shared__ float red[256];
    int tid = threadIdx.x;
    float acc = 0.0f;
    for (int i = tid; i < N_*C_; i += 256) {
        float s = d_sum[i], s2 = d_sumsq[i];
        float v = (s2 - s * s * (1.0f / HW_)) * (1.0f / (HW_ - 1));
        d_xv[i] = v;
        acc += v;
    }
    red[tid] = acc;
    __syncthreads();
    for (int off = 128; off; off >>= 1) {
        if (tid < off) red[tid] += red[tid + off];
        __syncthreads();
    }
    float m = 0.0f;
    #pragma unroll
    for (int n = 0; n < N_; ++n) m += d_sum[n * C_ + tid];
    d_mu[tid] = m * (1.0f / MTOT);
    if (tid == 0) {
        float w = 1.0f / (1.0f + expf(-xw[0]));
        d_w = w;
        d_coef = (1.0f - w) / sqrtf(red[0] * (1.0f / (N_*C_)));
    }
}

// ---------------- K3: MLP per batch row (32 blocks) ----------------
__global__ void k_mlp(const float* __restrict__ fc1, const float* __restrict__ lng,
                      const float* __restrict__ lnb, const float* __restrict__ fc2) {
    int n = blockIdx.x, tid = threadIdx.x;
    __shared__ float xv[C_];
    __shared__ float h[D_];
    __shared__ float rsum[64], rsq[64];

    xv[tid] = d_xv[n * C_ + tid];
    __syncthreads();

    // h[j] = dot(xv, fc1[j,:]) -- 4 lanes per j
    {
        int j = tid >> 2, p = tid & 3;
        const float* w = fc1 + j * C_ + p * 64;
        const float* x = xv + p * 64;
        float a = 0.0f;
        #pragma unroll 16
        for (int c = 0; c < 64; ++c) a += x[c] * w[c];
        a += __shfl_xor_sync(0xffffffffu, a, 1);
        a += __shfl_xor_sync(0xffffffffu, a, 2);
        if (p == 0) h[j] = a;
    }
    __syncthreads();

    // LayerNorm (biased) + affine + relu
    if (tid < 64) { float v = h[tid]; rsum[tid] = v; rsq[tid] = v * v; }
    __syncthreads();
    for (int off = 32; off; off >>= 1) {
        if (tid < off) { rsum[tid] += rsum[tid + off]; rsq[tid] += rsq[tid + off]; }
        __syncthreads();
    }
    float mu  = rsum[0] * (1.0f / D_);
    float var = rsq[0] * (1.0f / D_) - mu * mu;
    float inv = rsqrtf(var + LNEPS);
    if (tid < 64) {
        float v = (h[tid] - mu) * inv * lng[tid] + lnb[tid];
        h[tid] = v > 0.0f ? v : 0.0f;
    }
    __syncthreads();

    // y[c] = sigmoid(dot(h, fc2[c,:])); a = coef * y
    float a = 0.0f;
    const float* w2 = fc2 + tid * D_;
    #pragma unroll 16
    for (int j = 0; j < D_; ++j) a += h[j] * w2[j];
    d_a[n * C_ + tid] = d_coef / (1.0f + expf(-a));
}

// ---------------- K4: Newton-Schulz ----------------
__device__ __forceinline__ void mm64t(float* Cm, const float* A, const float* B,
                                      int tx, int ty) {
    float acc[4][4] = {};
    #pragma unroll 4
    for (int k = 0; k < 64; ++k) {
        float a0 = A[(ty     )*66 + k], a1 = A[(ty + 16)*66 + k];
        float a2 = A[(ty + 32)*66 + k], a3 = A[(ty + 48)*66 + k];
        float b0 = B[k*66 + tx], b1 = B[k*66 + tx + 16];
        float b2 = B[k*66 + tx + 32], b3 = B[k*66 + tx + 48];
        acc[0][0] += a0*b0; acc[0][1] += a0*b1; acc[0][2] += a0*b2; acc[0][3] += a0*b3;
        acc[1][0] += a1*b0; acc[1][1] += a1*b1; acc[1][2] += a1*b2; acc[1][3] += a1*b3;
        acc[2][0] += a2*b0; acc[2][1] += a2*b1; acc[2][2] += a2*b2; acc[2][3] += a2*b3;
        acc[3][0] += a3*b0; acc[3][1] += a3*b1; acc[3][2] += a3*b2; acc[3][3] += a3*b3;
    }
    #pragma unroll
    for (int i = 0; i < 4; ++i)
        #pragma unroll
        for (int j = 0; j < 4; ++j)
            Cm[(ty + 16*i)*66 + tx + 16*j] = acc[i][j];
}

__global__ void k_newton() {
    extern __shared__ float sm[];
    float* SigN = sm;
    float* P    = sm + 4224;
    float* T1   = sm + 8448;
    float* T2   = sm + 12672;
    __shared__ float s_invtr;
    int g = blockIdx.x, tid = threadIdx.x;
    int tx = tid & 15, ty = tid >> 4;
    float w = d_w;

    for (int t = 0; t < 16; ++t) {
        int idx = tid + t * 256;
        int d = idx >> 6, e = idx & 63;
        float v = EPSW * (d_gram[g*4096 + idx] - MTOT * d_mu[g*64 + d] * d_mu[g*64 + e]);
        if (d == e) v += 1.0f / MTOT;
        T1[d*66 + e] = v;
        P [d*66 + e] = (d == e) ? 1.0f : 0.0f;
    }
    __syncthreads();
    if (tid == 0) {
        float tr = 0.0f;
        for (int d = 0; d < 64; ++d) tr += T1[d*66 + d];
        s_invtr = 1.0f / tr;
    }
    __syncthreads();
    float invtr = s_invtr;
    for (int t = 0; t < 16; ++t) {
        int idx = tid + t * 256;
        int d = idx >> 6, e = idx & 63;
        SigN[d*66 + e] = T1[d*66 + e] * invtr;
    }
    __syncthreads();

    for (int it = 0; it < 3; ++it) {
        mm64t(T1, P, P, tx, ty);     __syncthreads();
        mm64t(T2, T1, P, tx, ty);    __syncthreads();
        mm64t(T1, T2, SigN, tx, ty); __syncthreads();
        for (int t = 0; t < 16; ++t) {
            int idx = tid + t * 256;
            int d = idx >> 6, e = idx & 63;
            P[d*66 + e] = -0.5f * P[d*66 + e] + 1.5f * T1[d*66 + e];
        }
        __syncthreads();
    }
    for (int t = 0; t < 16; ++t) {
        int idx = tid + t * 256;
        int d = idx >> 6, e = idx & 63;
        d_wP[g*4096 + idx] = w * P[d*66 + e];
    }
}

// ---------------- K5: out = (wP[g] + diag(a[n])) @ x ----------------
// grid (chunk=8, n=32, g=4), 256 threads, dynamic smem:
//   Md[64][130]: M[d][e] duplicated at (e*130 + 2d, +1) -> broadcast LDS.64
//   xs[64][66] : channel-major tile
__global__ void __launch_bounds__(256) k_apply(const float* __restrict__ X,
                                               float* __restrict__ out) {
    extern __shared__ __align__(16) float sm2[];
    float* Md = sm2;              // 64*130 = 8320 floats
    float* xs = sm2 + 8320;       // 64*66  = 4224 floats
    int chunk = blockIdx.x, n = blockIdx.y, g = blockIdx.z;
    int tid = threadIdx.x;
    int tx = tid & 15, ty = tid >> 4;

    for (int t = 0; t < 16; ++t) {
        int idx = tid + t * 256;
        int d = idx & 63, e = idx >> 6;
        float v = d_wP[g*4096 + d * 64 + e];
        if (d == e) v += d_a[n * C_ + g * 64 + d];
        *(float2*)&Md[e * 130 + 2 * d] = make_float2(v, v);
    }

    const float* base  = X   + ((size_t)n * C_ + (size_t)g * D_) * HW_ + chunk * 512;
    float*       obase = out + ((size_t)n * C_ + (size_t)g * D_) * HW_ + chunk * 512;

    for (int t = 0; t < 8; ++t) {
        const float* src = base + t * 64;
        __syncthreads();
        #pragma unroll
        for (int k = 0; k < 16; ++k) {
            int idx = tid + k * 256;
            int c = idx >> 6, s = idx & 63;
            xs[c * 66 + s] = src[(size_t)c * HW_ + s];
        }
        __syncthreads();

        ull acc[4][2] = {};
        const ull* xa = (const ull*)xs;   // float2 idx: e*33 + u
        const ull* Ma = (const ull*)Md;   // float2 idx: e*65 + d
        #pragma unroll 4
        for (int e = 0; e < 64; ++e) {
            ull b0 = xa[e*33 + tx], b1 = xa[e*33 + tx + 16];
            ull a0 = Ma[e*65 + ty],      a1 = Ma[e*65 + ty + 16];
            ull a2 = Ma[e*65 + ty + 32], a3 = Ma[e*65 + ty + 48];
            fma2(acc[0][0], a0, b0); fma2(acc[0][1], a0, b1);
            fma2(acc[1][0], a1, b0); fma2(acc[1][1], a1, b1);
            fma2(acc[2][0], a2, b0); fma2(acc[2][1], a2, b1);
            fma2(acc[3][0], a3, b0); fma2(acc[3][1], a3, b1);
        }
        float* dst = obase + t * 64;
        #pragma unroll
        for (int i = 0; i < 4; ++i) {
            int d = ty + 16 * i;
            *(float2*)(dst + (size_t)d * HW_ + 2*tx)      = u2f(acc[i][0]);
            *(float2*)(dst + (size_t)d * HW_ + 2*tx + 32) = u2f(acc[i][1]);
        }
    }
}

// ---------------- launch ----------------
extern "C" void kernel_launch(void* const* d_in, const int* in_sizes, int n_in,
                              void* d_out, int out_size) {
    const float* X   = (const float*)d_in[0];
    const float* fc1 = (const float*)d_in[1];
    const float* lng = (const float*)d_in[2];
    const float* lnb = (const float*)d_in[3];
    const float* fc2 = (const float*)d_in[4];
    const float* xw  = (const float*)d_in[5];
    float* out = (float*)d_out;

    static bool attr_set = false;
    if (!attr_set) {
        cudaFuncSetAttribute(k_newton, cudaFuncAttributeMaxDynamicSharedMemorySize, 69632);
        cudaFuncSetAttribute(k_apply,  cudaFuncAttributeMaxDynamicSharedMemorySize, 51200);
        attr_set = true;
    }

    k_zero  <<<128, 256>>>();
    k_gram  <<<dim3(4, 32, 4), 256>>>(X);
    k_prep  <<<1, 256>>>(xw);
    k_newton<<<G_, 256, 16896 * 4>>>();
    k_mlp   <<<N_, 256>>>(fc1, lng, lnb, fc2);
    k_apply <<<dim3(8, 32, 4), 256, 50176>>>(X, out);
}

// round 4
// speedup vs baseline: 3.2884x; 1.1082x over previous
#include <cuda_runtime.h>
#include <math.h>

#define N_   32
#define C_   256
#define HW_  4096
#define G_   4
#define D_   64
#define MTOT 131072.0f
#define EPSW 1e-5f
#define LNEPS 1e-5f

typedef unsigned long long ull;

__device__ __forceinline__ void fma2(ull& d, ull a, ull b) {
    asm("fma.rn.f32x2 %0, %1, %2, %0;" : "+l"(d) : "l"(a), "l"(b));
}
__device__ __forceinline__ void add2(ull& d, ull a) {
    asm("add.rn.f32x2 %0, %0, %1;" : "+l"(d) : "l"(a));
}
__device__ __forceinline__ float2 u2f(ull v) {
    float2 r;
    asm("mov.b64 {%0,%1}, %2;" : "=f"(r.x), "=f"(r.y) : "l"(v));
    return r;
}
__device__ __forceinline__ void cpa16(void* sdst, const void* gsrc) {
    unsigned s = (unsigned)__cvta_generic_to_shared(sdst);
    asm volatile("cp.async.ca.shared.global [%0], [%1], 16;" :: "r"(s), "l"(gsrc));
}
#define CP_COMMIT() asm volatile("cp.async.commit_group;")
#define CP_WAIT0()  asm volatile("cp.async.wait_group 0;")

// ---------------- device scratch ----------------
__device__ float d_sum  [N_*C_];
__device__ float d_sumsq[N_*C_];
__device__ float d_gram [G_*D_*D_];
__device__ float d_xv   [N_*C_];
__device__ float d_a    [N_*C_];
__device__ float d_mu   [C_];
__device__ float d_wP   [G_*D_*D_];
__device__ float d_w;
__device__ float d_coef;

// ---------------- K0: zero accumulators ----------------
__global__ void k_zero() {
    int i = blockIdx.x * blockDim.x + threadIdx.x;
    if (i < N_*C_) { d_sum[i] = 0.0f; d_sumsq[i] = 0.0f; }
    if (i < G_*D_*D_) d_gram[i] = 0.0f;
}

// ---------------- K1: gram + fused row stats (cp.async double-buffered) ----
// grid (chunk=4, n=32, g=4), 256 thr. tile = 64 positions x 64 channels.
// xs rows padded to 68 floats (16B-aligned rows, conflict-free f32x2 loads).
__global__ void __launch_bounds__(256) k_gram(const float* __restrict__ X) {
    __shared__ __align__(16) float xs[2][D_ * 68];
    __shared__ float rs[256], rs2[256];
    int chunk = blockIdx.x, n = blockIdx.y, g = blockIdx.z;
    int tid = threadIdx.x;
    int tx = tid & 15, ty = tid >> 4;
    int cs = tid & 63, q = tid >> 6;
    const float* base = X + ((size_t)n * C_ + (size_t)g * D_) * HW_ + chunk * 1024;

    ull acc[4][4] = {};
    ull s_acc = 0ull, s2_acc = 0ull;

    {   // prologue: tile 0 -> buf 0
        const float* src = base;
        #pragma unroll
        for (int k = 0; k < 4; ++k) {
            int pos = tid + k * 256;
            int c = pos >> 4, s4 = pos & 15;
            cpa16(&xs[0][c * 68 + s4 * 4], src + (size_t)c * HW_ + s4 * 4);
        }
        CP_COMMIT();
    }

    int buf = 0;
    for (int t = 0; t < 16; ++t) {
        CP_WAIT0();
        __syncthreads();                 // tile t visible; all done with buf^1
        if (t < 15) {
            const float* src = base + (t + 1) * 64;
            #pragma unroll
            for (int k = 0; k < 4; ++k) {
                int pos = tid + k * 256;
                int c = pos >> 4, s4 = pos & 15;
                cpa16(&xs[buf ^ 1][c * 68 + s4 * 4], src + (size_t)c * HW_ + s4 * 4);
            }
            CP_COMMIT();
        }
        const ull* xa = (const ull*)xs[buf];       // float2 stride 34 per row
        #pragma unroll 4
        for (int u = 0; u < 32; ++u) {
            ull a0 = xa[(ty     )*34 + u], a1 = xa[(ty + 16)*34 + u];
            ull a2 = xa[(ty + 32)*34 + u], a3 = xa[(ty + 48)*34 + u];
            ull b0 = xa[(tx     )*34 + u], b1 = xa[(tx + 16)*34 + u];
            ull b2 = xa[(tx + 32)*34 + u], b3 = xa[(tx + 48)*34 + u];
            fma2(acc[0][0], a0, b0); fma2(acc[0][1], a0, b1);
            fma2(acc[0][2], a0, b2); fma2(acc[0][3], a0, b3);
            fma2(acc[1][0], a1, b0); fma2(acc[1][1], a1, b1);
            fma2(acc[1][2], a1, b2); fma2(acc[1][3], a1, b3);
            fma2(acc[2][0], a2, b0); fma2(acc[2][1], a2, b1);
            fma2(acc[2][2], a2, b2); fma2(acc[2][3], a2, b3);
            fma2(acc[3][0], a3, b0); fma2(acc[3][1], a3, b1);
            fma2(acc[3][2], a3, b2); fma2(acc[3][3], a3, b3);
        }
        #pragma unroll
        for (int u = 8 * q; u < 8 * q + 8; ++u) {
            ull v = xa[cs * 34 + u];
            add2(s_acc, v);
            fma2(s2_acc, v, v);
        }
        buf ^= 1;
    }

    float2 sv = u2f(s_acc), s2v = u2f(s2_acc);
    rs[tid] = sv.x + sv.y; rs2[tid] = s2v.x + s2v.y;
    __syncthreads();
    if (tid < 64) {
        float a = rs[tid] + rs[tid+64] + rs[tid+128] + rs[tid+192];
        float b = rs2[tid] + rs2[tid+64] + rs2[tid+128] + rs2[tid+192];
        atomicAdd(&d_sum  [n * C_ + g * 64 + tid], a);
        atomicAdd(&d_sumsq[n * C_ + g * 64 + tid], b);
    }
    float* gp = d_gram + g * D_ * D_;
    #pragma unroll
    for (int i = 0; i < 4; ++i)
        #pragma unroll
        for (int j = 0; j < 4; ++j) {
            float2 f = u2f(acc[i][j]);
            atomicAdd(&gp[(ty + 16*i) * D_ + tx + 16*j], f.x + f.y);
        }
}

// ---------------- K2: xvar, scale, mu, w (tiny) ----------------
__global__ void k_prep(const float* __restrict__ xw) {
    __shared__ float red[256];
    int tid = threadIdx.x;
    float acc = 0.0f;
    for (int i = tid; i < N_*C_; i += 256) {
        float s = d_sum[i], s2 = d_sumsq[i];
        float v = (s2 - s * s * (1.0f / HW_)) * (1.0f / (HW_ - 1));
        d_xv[i] = v;
        acc += v;
    }
    red[tid] = acc;
    __syncthreads();
    for (int off = 128; off; off >>= 1) {
        if (tid < off) red[tid] += red[tid + off];
        __syncthreads();
    }
    float m = 0.0f;
    #pragma unroll
    for (int n = 0; n < N_; ++n) m += d_sum[n * C_ + tid];
    d_mu[tid] = m * (1.0f / MTOT);
    if (tid == 0) {
        float w = 1.0f / (1.0f + expf(-xw[0]));
        d_w = w;
        d_coef = (1.0f - w) / sqrtf(red[0] * (1.0f / (N_*C_)));
    }
}

// ---------------- K3: MLP per batch row ----------------
__global__ void k_mlp(const float* __restrict__ fc1, const float* __restrict__ lng,
                      const float* __restrict__ lnb, const float* __restrict__ fc2) {
    int n = blockIdx.x, tid = threadIdx.x;
    __shared__ float xv[C_];
    __shared__ float h[D_];
    __shared__ float rsum[64], rsq[64];

    xv[tid] = d_xv[n * C_ + tid];
    __syncthreads();
    {
        int j = tid >> 2, p = tid & 3;
        const float* w = fc1 + j * C_ + p * 64;
        const float* x = xv + p * 64;
        float a = 0.0f;
        #pragma unroll 16
        for (int c = 0; c < 64; ++c) a += x[c] * w[c];
        a += __shfl_xor_sync(0xffffffffu, a, 1);
        a += __shfl_xor_sync(0xffffffffu, a, 2);
        if (p == 0) h[j] = a;
    }
    __syncthreads();
    if (tid < 64) { float v = h[tid]; rsum[tid] = v; rsq[tid] = v * v; }
    __syncthreads();
    for (int off = 32; off; off >>= 1) {
        if (tid < off) { rsum[tid] += rsum[tid + off]; rsq[tid] += rsq[tid + off]; }
        __syncthreads();
    }
    float mu  = rsum[0] * (1.0f / D_);
    float var = rsq[0] * (1.0f / D_) - mu * mu;
    float inv = rsqrtf(var + LNEPS);
    if (tid < 64) {
        float v = (h[tid] - mu) * inv * lng[tid] + lnb[tid];
        h[tid] = v > 0.0f ? v : 0.0f;
    }
    __syncthreads();
    float a = 0.0f;
    const float* w2 = fc2 + tid * D_;
    #pragma unroll 16
    for (int j = 0; j < D_; ++j) a += h[j] * w2[j];
    d_a[n * C_ + tid] = d_coef / (1.0f + expf(-a));
}

// ---------------- K4: Newton-Schulz (512 thr, P0=I shortcut: 6 matmuls) ----
__device__ __forceinline__ void mm64t(float* Cm, const float* A, const float* B,
                                      int tx, int ty) {
    float acc[2][4] = {};
    #pragma unroll 4
    for (int k = 0; k < 64; ++k) {
        float a0 = A[ty*66 + k], a1 = A[(ty + 32)*66 + k];
        float b0 = B[k*66 + tx],      b1 = B[k*66 + tx + 16];
        float b2 = B[k*66 + tx + 32], b3 = B[k*66 + tx + 48];
        acc[0][0] += a0*b0; acc[0][1] += a0*b1; acc[0][2] += a0*b2; acc[0][3] += a0*b3;
        acc[1][0] += a1*b0; acc[1][1] += a1*b1; acc[1][2] += a1*b2; acc[1][3] += a1*b3;
    }
    #pragma unroll
    for (int i = 0; i < 2; ++i)
        #pragma unroll
        for (int j = 0; j < 4; ++j)
            Cm[(ty + 32*i)*66 + tx + 16*j] = acc[i][j];
}

__global__ void __launch_bounds__(512) k_newton() {
    extern __shared__ float sm[];
    float* SigN = sm;
    float* P    = sm + 4224;
    float* T1   = sm + 8448;
    float* T2   = sm + 12672;
    __shared__ float s_invtr;
    int g = blockIdx.x, tid = threadIdx.x;
    int tx = tid & 15, ty = tid >> 4;
    float w = d_w;

    for (int t = 0; t < 8; ++t) {
        int idx = tid + t * 512;
        int d = idx >> 6, e = idx & 63;
        float v = EPSW * (d_gram[g*4096 + idx] - MTOT * d_mu[g*64 + d] * d_mu[g*64 + e]);
        if (d == e) v += 1.0f / MTOT;
        T1[d*66 + e] = v;
    }
    __syncthreads();
    if (tid == 0) {
        float tr = 0.0f;
        for (int d = 0; d < 64; ++d) tr += T1[d*66 + d];
        s_invtr = 1.0f / tr;
    }
    __syncthreads();
    float invtr = s_invtr;
    // SigN; P1 = -0.5 I + 1.5 SigN (first NS iteration is free since P0 = I)
    for (int t = 0; t < 8; ++t) {
        int idx = tid + t * 512;
        int d = idx >> 6, e = idx & 63;
        float s = T1[d*66 + e] * invtr;
        SigN[d*66 + e] = s;
        P[d*66 + e] = 1.5f * s + ((d == e) ? -0.5f : 0.0f);
    }
    __syncthreads();

    for (int it = 0; it < 2; ++it) {
        mm64t(T1, P, P, tx, ty);     __syncthreads();
        mm64t(T2, T1, P, tx, ty);    __syncthreads();
        mm64t(T1, T2, SigN, tx, ty); __syncthreads();
        for (int t = 0; t < 8; ++t) {
            int idx = tid + t * 512;
            int d = idx >> 6, e = idx & 63;
            P[d*66 + e] = -0.5f * P[d*66 + e] + 1.5f * T1[d*66 + e];
        }
        __syncthreads();
    }
    for (int t = 0; t < 8; ++t) {
        int idx = tid + t * 512;
        int d = idx >> 6, e = idx & 63;
        d_wP[g*4096 + idx] = w * P[d*66 + e];
    }
}

// ---------------- K5: out = (wP[g] + diag(a[n])) @ x (cp.async dbuf) -------
// dyn smem: xs[2][64*68] then Md[64*130] (M duplicated pairs for LDS.64 bcast)
__global__ void __launch_bounds__(256) k_apply(const float* __restrict__ X,
                                               float* __restrict__ out) {
    extern __shared__ __align__(16) float sm2[];
    float* xs0 = sm2;
    float* xs1 = sm2 + 4352;
    float* Md  = sm2 + 8704;
    int chunk = blockIdx.x, n = blockIdx.y, g = blockIdx.z;
    int tid = threadIdx.x;
    int tx = tid & 15, ty = tid >> 4;

    const float* base  = X   + ((size_t)n * C_ + (size_t)g * D_) * HW_ + chunk * 512;
    float*       obase = out + ((size_t)n * C_ + (size_t)g * D_) * HW_ + chunk * 512;

    {   // prologue copy tile 0
        #pragma unroll
        for (int k = 0; k < 4; ++k) {
            int pos = tid + k * 256;
            int c = pos >> 4, s4 = pos & 15;
            cpa16(xs0 + c * 68 + s4 * 4, base + (size_t)c * HW_ + s4 * 4);
        }
        CP_COMMIT();
    }
    // build Md while copy 0 is in flight
    for (int t = 0; t < 16; ++t) {
        int idx = tid + t * 256;
        int d = idx & 63, e = idx >> 6;
        float v = d_wP[g*4096 + d * 64 + e];
        if (d == e) v += d_a[n * C_ + g * 64 + d];
        *(float2*)&Md[e * 130 + 2 * d] = make_float2(v, v);
    }

    float* bufs[2] = { xs0, xs1 };
    int buf = 0;
    for (int t = 0; t < 8; ++t) {
        CP_WAIT0();
        __syncthreads();
        if (t < 7) {
            const float* src = base + (t + 1) * 64;
            float* db = bufs[buf ^ 1];
            #pragma unroll
            for (int k = 0; k < 4; ++k) {
                int pos = tid + k * 256;
                int c = pos >> 4, s4 = pos & 15;
                cpa16(db + c * 68 + s4 * 4, src + (size_t)c * HW_ + s4 * 4);
            }
            CP_COMMIT();
        }
        ull acc[4][2] = {};
        const ull* xa = (const ull*)bufs[buf];   // stride 34
        const ull* Ma = (const ull*)Md;          // stride 65
        #pragma unroll 4
        for (int e = 0; e < 64; ++e) {
            ull b0 = xa[e*34 + tx], b1 = xa[e*34 + tx + 16];
            ull a0 = Ma[e*65 + ty],      a1 = Ma[e*65 + ty + 16];
            ull a2 = Ma[e*65 + ty + 32], a3 = Ma[e*65 + ty + 48];
            fma2(acc[0][0], a0, b0); fma2(acc[0][1], a0, b1);
            fma2(acc[1][0], a1, b0); fma2(acc[1][1], a1, b1);
            fma2(acc[2][0], a2, b0); fma2(acc[2][1], a2, b1);
            fma2(acc[3][0], a3, b0); fma2(acc[3][1], a3, b1);
        }
        float* dst = obase + t * 64;
        #pragma unroll
        for (int i = 0; i < 4; ++i) {
            int d = ty + 16 * i;
            *(float2*)(dst + (size_t)d * HW_ + 2*tx)      = u2f(acc[i][0]);
            *(float2*)(dst + (size_t)d * HW_ + 2*tx + 32) = u2f(acc[i][1]);
        }
        buf ^= 1;
    }
}

// ---------------- launch ----------------
extern "C" void kernel_launch(void* const* d_in, const int* in_sizes, int n_in,
                              void* d_out, int out_size) {
    const float* X   = (const float*)d_in[0];
    const float* fc1 = (const float*)d_in[1];
    const float* lng = (const float*)d_in[2];
    const float* lnb = (const float*)d_in[3];
    const float* fc2 = (const float*)d_in[4];
    const float* xw  = (const float*)d_in[5];
    float* out = (float*)d_out;

    static bool attr_set = false;
    if (!attr_set) {
        cudaFuncSetAttribute(k_newton, cudaFuncAttributeMaxDynamicSharedMemorySize, 69632);
        cudaFuncSetAttribute(k_apply,  cudaFuncAttributeMaxDynamicSharedMemorySize, 69632);
        attr_set = true;
    }

    k_zero  <<<128, 256>>>();
    k_gram  <<<dim3(4, 32, 4), 256>>>(X);
    k_prep  <<<1, 256>>>(xw);
    k_mlp   <<<N_, 256>>>(fc1, lng, lnb, fc2);
    k_newton<<<G_, 512, 67584>>>();
    k_apply <<<dim3(8, 32, 4), 256, 68096>>>(X, out);
}